// round 1
// baseline (speedup 1.0000x reference)
#include <cuda_runtime.h>
#include <math_constants.h>

// Problem constants
#define B_   32
#define T_   2048
#define HE_  1024
#define DECF 2048          // hid_flat width
#define S_   8             // T splits
#define CHUNK (T_ / S_)    // 256 timesteps per block
#define TILE 8             // rows per register tile
#define NT  256            // threads per block

// Scratch for split partials (allocation-free: __device__ globals)
__device__ float g_m  [B_ * S_];
__device__ float g_z  [B_ * S_];
__device__ float g_acc[B_ * S_ * HE_];

__global__ __launch_bounds__(NT)
void attn_pass1(const float* __restrict__ hidden,        // (2,32,1024)
                const float* __restrict__ enc,           // (32,2048,1024)
                const float* __restrict__ mask,          // (32,2048)
                const float* __restrict__ attn_w,        // (3072,)
                const float* __restrict__ attn_b)        // (1,)
{
    const int b   = blockIdx.x;
    const int s   = blockIdx.y;
    const int tid = threadIdx.x;
    const int wid = tid >> 5;
    const int lane = tid & 31;
    const int c0  = tid * 4;            // 4 channels per thread

    __shared__ float part[TILE * NT];   // per-row partial dots
    __shared__ float e_sh[TILE];        // masked energies per tile row
    __shared__ float msk_sh[TILE];      // mask values per tile row
    __shared__ float wsum[NT / 32];
    __shared__ float hid_sh;

    // ---- hid_dot[b] = hid_flat[b,:] @ w_h + attn_b (redundant per block, cheap) ----
    {
        float ps = 0.f;
        #pragma unroll
        for (int k = 0; k < DECF / NT; ++k) {
            int f = tid + k * NT;          // 0..2047
            int d = f >> 10;               // which decoder slice
            int c = f & 1023;
            ps += hidden[(size_t)d * (B_ * HE_) + (size_t)b * HE_ + c] * attn_w[f];
        }
        #pragma unroll
        for (int o = 16; o > 0; o >>= 1) ps += __shfl_xor_sync(0xffffffffu, ps, o);
        if (lane == 0) wsum[wid] = ps;
        __syncthreads();
        if (tid == 0) {
            float h = attn_b[0];
            #pragma unroll
            for (int w = 0; w < NT / 32; ++w) h += wsum[w];
            hid_sh = h;
        }
        __syncthreads();
    }
    const float hid_dot = hid_sh;

    // w_e for this thread's 4 channels
    const float4 we = *reinterpret_cast<const float4*>(attn_w + DECF + c0);

    // ---- online softmax-weighted accumulation over CHUNK rows ----
    float m = -CUDART_INF_F;
    float z = 0.f;
    float4 acc = make_float4(0.f, 0.f, 0.f, 0.f);

    const int t_base = s * CHUNK;
    const float* encB = enc + (size_t)b * T_ * HE_;
    const float* mskB = mask + (size_t)b * T_;

    for (int tile = 0; tile < CHUNK / TILE; ++tile) {
        const int t0 = t_base + tile * TILE;

        float4 v[TILE];
        float  pd[TILE];
        #pragma unroll
        for (int u = 0; u < TILE; ++u) {
            v[u] = *reinterpret_cast<const float4*>(encB + (size_t)(t0 + u) * HE_ + c0);
            pd[u] = v[u].x * we.x + v[u].y * we.y + v[u].z * we.z + v[u].w * we.w;
        }
        #pragma unroll
        for (int u = 0; u < TILE; ++u) part[u * NT + tid] = pd[u];
        __syncthreads();

        // warp w reduces row u = w (TILE == 8 warps)
        {
            float sum = 0.f;
            #pragma unroll
            for (int k = 0; k < NT / 32; ++k) sum += part[wid * NT + lane + 32 * k];
            #pragma unroll
            for (int o = 16; o > 0; o >>= 1) sum += __shfl_xor_sync(0xffffffffu, sum, o);
            if (lane == 0) {
                float mk = mskB[t0 + wid];
                msk_sh[wid] = mk;
                e_sh[wid] = (sum + hid_dot) * mk;   // masked energy e'
            }
        }
        __syncthreads();

        float e_loc[TILE], mk_loc[TILE];
        float mnew = m;
        #pragma unroll
        for (int u = 0; u < TILE; ++u) {
            e_loc[u]  = e_sh[u];
            mk_loc[u] = msk_sh[u];
            mnew = fmaxf(mnew, e_loc[u]);
        }
        const float scale = __expf(m - mnew);
        z *= scale;
        acc.x *= scale; acc.y *= scale; acc.z *= scale; acc.w *= scale;
        #pragma unroll
        for (int u = 0; u < TILE; ++u) {
            const float wt = mk_loc[u] * __expf(e_loc[u] - mnew);
            z += wt;
            acc.x += wt * v[u].x;
            acc.y += wt * v[u].y;
            acc.z += wt * v[u].z;
            acc.w += wt * v[u].w;
        }
        m = mnew;
        __syncthreads();   // part[] reuse next tile
    }

    // ---- write split partials ----
    const int ps_idx = b * S_ + s;
    *reinterpret_cast<float4*>(g_acc + (size_t)ps_idx * HE_ + c0) = acc;
    if (tid == 0) { g_m[ps_idx] = m; g_z[ps_idx] = z; }
}

__global__ __launch_bounds__(NT)
void attn_pass2(float* __restrict__ out)   // (32,1024)
{
    const int b   = blockIdx.x;
    const int tid = threadIdx.x;
    const int c0  = tid * 4;

    float ms[S_], zs[S_];
    float M = -CUDART_INF_F;
    #pragma unroll
    for (int s = 0; s < S_; ++s) {
        ms[s] = g_m[b * S_ + s];
        zs[s] = g_z[b * S_ + s];
        M = fmaxf(M, ms[s]);
    }
    float es[S_];
    float Z = 0.f;
    #pragma unroll
    for (int s = 0; s < S_; ++s) {
        es[s] = __expf(ms[s] - M);
        Z += es[s] * zs[s];
    }

    float4 o = make_float4(0.f, 0.f, 0.f, 0.f);
    #pragma unroll
    for (int s = 0; s < S_; ++s) {
        const float4 a = *reinterpret_cast<const float4*>(g_acc + (size_t)(b * S_ + s) * HE_ + c0);
        o.x += es[s] * a.x;
        o.y += es[s] * a.y;
        o.z += es[s] * a.z;
        o.w += es[s] * a.w;
    }
    const float inv = 1.f / Z;
    o.x *= inv; o.y *= inv; o.z *= inv; o.w *= inv;
    *reinterpret_cast<float4*>(out + (size_t)b * HE_ + c0) = o;
}

extern "C" void kernel_launch(void* const* d_in, const int* in_sizes, int n_in,
                              void* d_out, int out_size)
{
    const float* hidden = (const float*)d_in[0];
    const float* enc    = (const float*)d_in[1];
    const float* mask   = (const float*)d_in[2];
    const float* attn_w = (const float*)d_in[3];
    const float* attn_b = (const float*)d_in[4];
    float* out = (float*)d_out;

    attn_pass1<<<dim3(B_, S_), NT>>>(hidden, enc, mask, attn_w, attn_b);
    attn_pass2<<<B_, NT>>>(out);
}

// round 3
// speedup vs baseline: 1.1231x; 1.1231x over previous
#include <cuda_runtime.h>
#include <math_constants.h>

#define B_    32
#define T_    2048
#define HE_   1024
#define DECF  2048
#define S_    16
#define CHUNK (T_ / S_)          // 128 rows per CTA
#define NW    4                  // warps per CTA
#define NT    (NW * 32)          // 128 threads
#define RPW   (CHUNK / NW)       // 32 rows per warp

// Split partials (allocation-free scratch)
__device__ float g_m  [B_ * S_];
__device__ float g_z  [B_ * S_];
__device__ __align__(16) float g_acc[B_ * S_ * HE_];

__global__ __launch_bounds__(NT, 4)
void attn_pass1(const float* __restrict__ hidden,   // (2,32,1024)
                const float* __restrict__ enc,      // (32,2048,1024)
                const float* __restrict__ mask,     // (32,2048)
                const float* __restrict__ attn_w,   // (3072,)
                const float* __restrict__ attn_b)   // (1,)
{
    const int b    = blockIdx.x;
    const int s    = blockIdx.y;
    const int tid  = threadIdx.x;
    const int wid  = tid >> 5;
    const int lane = tid & 31;

    __shared__ float s_red[NW];
    __shared__ float s_hid;
    __shared__ float s_m[NW], s_z[NW];
    __shared__ __align__(16) float s_acc[NW * HE_];   // 16 KB

    // ---- hid_dot[b] = hid_flat[b,:] @ w_h + attn_b ----
    {
        float ps = 0.f;
        #pragma unroll
        for (int k = 0; k < DECF / NT; ++k) {
            const int f = tid + k * NT;               // 0..2047
            ps += hidden[(size_t)(f >> 10) * (B_ * HE_) + (size_t)b * HE_ + (f & 1023)]
                  * attn_w[f];
        }
        #pragma unroll
        for (int o = 16; o > 0; o >>= 1) ps += __shfl_xor_sync(0xffffffffu, ps, o);
        if (lane == 0) s_red[wid] = ps;
        __syncthreads();
        if (tid == 0) {
            float h = attn_b[0];
            #pragma unroll
            for (int w = 0; w < NW; ++w) h += s_red[w];
            s_hid = h;
        }
        __syncthreads();
    }
    const float hid_dot = s_hid;

    // w_e slice for this lane: channels lane*4 + 128*k
    float4 we[8];
    #pragma unroll
    for (int k = 0; k < 8; ++k)
        we[k] = *reinterpret_cast<const float4*>(attn_w + DECF + lane * 4 + k * 128);

    // ---- warp-private online softmax over RPW contiguous rows (no barriers) ----
    float m = -CUDART_INF_F;
    float z = 0.f;
    float4 acc[8];
    #pragma unroll
    for (int k = 0; k < 8; ++k) acc[k] = make_float4(0.f, 0.f, 0.f, 0.f);

    const int r0 = s * CHUNK + wid * RPW;
    const float* encB = enc  + (size_t)b * T_ * HE_;
    const float* mskB = mask + (size_t)b * T_;

    for (int i = 0; i < RPW; ++i) {
        const int r = r0 + i;
        const float* row = encB + (size_t)r * HE_ + lane * 4;

        float4 v[8];
        #pragma unroll
        for (int k = 0; k < 8; ++k)
            v[k] = *reinterpret_cast<const float4*>(row + k * 128);

        float d = 0.f;
        #pragma unroll
        for (int k = 0; k < 8; ++k)
            d += v[k].x * we[k].x + v[k].y * we[k].y + v[k].z * we[k].z + v[k].w * we[k].w;
        #pragma unroll
        for (int o = 16; o > 0; o >>= 1) d += __shfl_xor_sync(0xffffffffu, d, o);

        const float mk = __ldg(mskB + r);
        const float e  = (d + hid_dot) * mk;

        const float mnew = fmaxf(m, e);
        if (mnew > m) {                     // warp-uniform branch
            const float sc = __expf(m - mnew);
            z *= sc;
            #pragma unroll
            for (int k = 0; k < 8; ++k) {
                acc[k].x *= sc; acc[k].y *= sc; acc[k].z *= sc; acc[k].w *= sc;
            }
            m = mnew;
        }
        const float wt = mk * __expf(e - m);
        z += wt;
        #pragma unroll
        for (int k = 0; k < 8; ++k) {
            acc[k].x += wt * v[k].x;
            acc[k].y += wt * v[k].y;
            acc[k].z += wt * v[k].z;
            acc[k].w += wt * v[k].w;
        }
    }

    // ---- block combine (once) ----
    #pragma unroll
    for (int k = 0; k < 8; ++k)
        *reinterpret_cast<float4*>(&s_acc[wid * HE_ + lane * 4 + k * 128]) = acc[k];
    if (lane == 0) { s_m[wid] = m; s_z[wid] = z; }
    __syncthreads();

    const float M = fmaxf(fmaxf(s_m[0], s_m[1]), fmaxf(s_m[2], s_m[3]));
    float ew[NW];
    float Z = 0.f;
    #pragma unroll
    for (int w = 0; w < NW; ++w) {
        ew[w] = __expf(s_m[w] - M);
        Z += ew[w] * s_z[w];
    }

    // each thread combines 8 channels: c0 = tid*8
    float4 o0 = make_float4(0.f, 0.f, 0.f, 0.f);
    float4 o1 = make_float4(0.f, 0.f, 0.f, 0.f);
    #pragma unroll
    for (int w = 0; w < NW; ++w) {
        const float4 a0 = *reinterpret_cast<const float4*>(&s_acc[w * HE_ + tid * 8]);
        const float4 a1 = *reinterpret_cast<const float4*>(&s_acc[w * HE_ + tid * 8 + 4]);
        o0.x += ew[w] * a0.x; o0.y += ew[w] * a0.y; o0.z += ew[w] * a0.z; o0.w += ew[w] * a0.w;
        o1.x += ew[w] * a1.x; o1.y += ew[w] * a1.y; o1.z += ew[w] * a1.z; o1.w += ew[w] * a1.w;
    }
    const int ps_idx = b * S_ + s;
    *reinterpret_cast<float4*>(g_acc + (size_t)ps_idx * HE_ + tid * 8)     = o0;
    *reinterpret_cast<float4*>(g_acc + (size_t)ps_idx * HE_ + tid * 8 + 4) = o1;
    if (tid == 0) { g_m[ps_idx] = M; g_z[ps_idx] = Z; }
}

__global__ __launch_bounds__(128)
void attn_pass2(float* __restrict__ out)   // (32,1024)
{
    const int b    = blockIdx.x >> 1;
    const int half = blockIdx.x & 1;
    const int c0   = half * 512 + threadIdx.x * 4;

    float ms[S_], zs[S_];
    float M = -CUDART_INF_F;
    #pragma unroll
    for (int s = 0; s < S_; ++s) {
        ms[s] = g_m[b * S_ + s];
        zs[s] = g_z[b * S_ + s];
        M = fmaxf(M, ms[s]);
    }
    float es[S_];
    float Z = 0.f;
    #pragma unroll
    for (int s = 0; s < S_; ++s) {
        es[s] = __expf(ms[s] - M);
        Z += es[s] * zs[s];
    }

    float4 o = make_float4(0.f, 0.f, 0.f, 0.f);
    #pragma unroll
    for (int s = 0; s < S_; ++s) {
        const float4 a = *reinterpret_cast<const float4*>(
            g_acc + (size_t)(b * S_ + s) * HE_ + c0);
        o.x += es[s] * a.x;
        o.y += es[s] * a.y;
        o.z += es[s] * a.z;
        o.w += es[s] * a.w;
    }
    const float inv = 1.f / Z;
    o.x *= inv; o.y *= inv; o.z *= inv; o.w *= inv;
    *reinterpret_cast<float4*>(out + (size_t)b * HE_ + c0) = o;
}

extern "C" void kernel_launch(void* const* d_in, const int* in_sizes, int n_in,
                              void* d_out, int out_size)
{
    const float* hidden = (const float*)d_in[0];
    const float* enc    = (const float*)d_in[1];
    const float* mask   = (const float*)d_in[2];
    const float* attn_w = (const float*)d_in[3];
    const float* attn_b = (const float*)d_in[4];
    float* out = (float*)d_out;

    attn_pass1<<<dim3(B_, S_), NT>>>(hidden, enc, mask, attn_w, attn_b);
    attn_pass2<<<64, 128>>>(out);
}